// round 2
// baseline (speedup 1.0000x reference)
#include <cuda_runtime.h>

#define M_DIM 2048
#define N_DIM 8192
#define N_ITERS 1000
#define TAU 1e-4f
#define SIGMA 1e-4f
#define NBLK 148
#define NTHR 512
#define NWARP (NTHR / 32)

// Persistent state (allocation-free scratch: __device__ globals)
__device__ float g_x[N_DIM];
__device__ float g_xbar[N_DIM];
__device__ float g_y[M_DIM];
__device__ float g_lam[M_DIM];
__device__ unsigned int g_count;
__device__ unsigned int g_gen;

// ---------------------------------------------------------------------------
// Graph node 1: deterministic state reset on every replay
// ---------------------------------------------------------------------------
__global__ void init_kernel() {
    int i = blockIdx.x * blockDim.x + threadIdx.x;
    if (i < N_DIM) { g_x[i] = 0.f; g_xbar[i] = 0.f; }
    if (i < M_DIM) { g_y[i] = 0.f; }
    if (i == 0)    { g_count = 0u; g_gen = 0u; }
}

// ---------------------------------------------------------------------------
// Software grid barrier (sense via monotonically increasing generation).
// All NBLK blocks are guaranteed co-resident (NBLK <= SM count, 1 block/SM).
// ---------------------------------------------------------------------------
__device__ __forceinline__ void grid_sync() {
    __syncthreads();
    if (threadIdx.x == 0) {
        volatile unsigned int* vgen = &g_gen;
        unsigned int gen = *vgen;
        __threadfence();                       // release our writes GPU-wide
        unsigned int t = atomicAdd(&g_count, 1u);
        if (t == NBLK - 1) {
            g_count = 0u;
            __threadfence();
            atomicAdd(&g_gen, 1u);             // release all
        } else {
            while (*vgen == gen) { }           // spin (L2 poll)
        }
        __threadfence();                       // acquire
    }
    __syncthreads();
}

// ---------------------------------------------------------------------------
// Graph node 2: the entire PDHG solve in one persistent kernel.
//   Phase Y: warp per row (2048 rows over 2368 warps), xbar staged in smem.
//   Phase X: blocks 0..127 each own 64 columns; 8 row-groups x 64 cols,
//            coalesced column access, y staged in smem.
// ---------------------------------------------------------------------------
__global__ void __launch_bounds__(NTHR, 1)
pdhg_kernel(const float* __restrict__ A, const float* __restrict__ b,
            const float* __restrict__ c, float* __restrict__ out) {
    __shared__ float s_vec[N_DIM];     // 32 KB: xbar stage
    __shared__ float s_y[M_DIM];       // 8 KB: y / lam stage
    __shared__ float s_part[8][64];    // 2 KB: column partial sums

    const int tid  = threadIdx.x;
    const int warp = tid >> 5;
    const int lane = tid & 31;
    const int gw   = blockIdx.x * NWARP + warp;   // global warp id

    float4* s4 = reinterpret_cast<float4*>(s_vec);

    for (int it = 0; it < N_ITERS; it++) {
        // ---- Phase Y: y = min(0, y + SIGMA*(A @ xbar) - SIGMA*b) ----
        {
            const float4* x4 = reinterpret_cast<const float4*>(g_xbar);
            #pragma unroll
            for (int k = 0; k < (N_DIM / 4) / NTHR; k++)
                s4[tid + k * NTHR] = x4[tid + k * NTHR];
        }
        __syncthreads();

        if (gw < M_DIM) {
            const float4* Arow = reinterpret_cast<const float4*>(A + (size_t)gw * N_DIM);
            float acc = 0.f;
            #pragma unroll 8
            for (int k = lane; k < N_DIM / 4; k += 32) {
                float4 a  = Arow[k];
                float4 xb = s4[k];
                acc += a.x * xb.x + a.y * xb.y + a.z * xb.z + a.w * xb.w;
            }
            #pragma unroll
            for (int o = 16; o > 0; o >>= 1)
                acc += __shfl_down_sync(0xffffffffu, acc, o);
            if (lane == 0)
                g_y[gw] = fminf(0.f, g_y[gw] + SIGMA * acc - SIGMA * b[gw]);
        }
        grid_sync();

        // ---- Phase X: x = relu(x - TAU*(A^T @ y) - TAU*c); xbar = 2x - x_old ----
        #pragma unroll
        for (int k = 0; k < M_DIM / NTHR; k++)
            s_y[tid + k * NTHR] = g_y[tid + k * NTHR];
        __syncthreads();

        if (blockIdx.x < N_DIM / 64) {
            const int rg = tid >> 6;          // 0..7 row-group
            const int jc = tid & 63;          // column within block
            const int j  = blockIdx.x * 64 + jc;
            float acc = 0.f;
            #pragma unroll 8
            for (int i = rg; i < M_DIM; i += 8)
                acc += A[(size_t)i * N_DIM + j] * s_y[i];
            s_part[rg][jc] = acc;
            __syncthreads();
            if (rg == 0) {
                float dot = 0.f;
                #pragma unroll
                for (int r = 0; r < 8; r++) dot += s_part[r][jc];
                float xo = g_x[j];
                float xn = fmaxf(0.f, xo - TAU * dot - TAU * c[j]);
                g_x[j]    = xn;
                g_xbar[j] = 2.f * xn - xo;
            }
        }
        grid_sync();
    }

    // ---- Finalize: out = [x, lam, nu] ----
    for (int i = blockIdx.x * NTHR + tid; i < N_DIM; i += NBLK * NTHR)
        out[i] = g_x[i];
    for (int i = blockIdx.x * NTHR + tid; i < M_DIM; i += NBLK * NTHR) {
        float l = fmaxf(0.f, -g_y[i]);
        g_lam[i] = l;
        out[N_DIM + i] = l;
    }
    grid_sync();

    // nu = relu(c - A^T @ lam): same structure as phase X
    #pragma unroll
    for (int k = 0; k < M_DIM / NTHR; k++)
        s_y[tid + k * NTHR] = g_lam[tid + k * NTHR];
    __syncthreads();

    if (blockIdx.x < N_DIM / 64) {
        const int rg = tid >> 6;
        const int jc = tid & 63;
        const int j  = blockIdx.x * 64 + jc;
        float acc = 0.f;
        #pragma unroll 8
        for (int i = rg; i < M_DIM; i += 8)
            acc += A[(size_t)i * N_DIM + j] * s_y[i];
        s_part[rg][jc] = acc;
        __syncthreads();
        if (rg == 0) {
            float dot = 0.f;
            #pragma unroll
            for (int r = 0; r < 8; r++) dot += s_part[r][jc];
            out[N_DIM + M_DIM + j] = fmaxf(0.f, c[j] - dot);
        }
    }
}

// ---------------------------------------------------------------------------
// kernel_launch: 2 graph nodes total (no multi-MB graph upload buffer).
// Inputs (metadata order): c (8192), A (2048*8192), b (2048).
// Output: 18432 floats = concat(x[8192], lam[2048], nu[8192]).
// ---------------------------------------------------------------------------
extern "C" void kernel_launch(void* const* d_in, const int* in_sizes, int n_in,
                              void* d_out, int out_size) {
    const float* c = (const float*)d_in[0];
    const float* A = (const float*)d_in[1];
    const float* b = (const float*)d_in[2];
    float* out = (float*)d_out;

    init_kernel<<<N_DIM / 256, 256>>>();
    pdhg_kernel<<<NBLK, NTHR>>>(A, b, c, out);
}